// round 5
// baseline (speedup 1.0000x reference)
#include <cuda_runtime.h>
#include <math.h>

#define NB 8
#define NM 64
#define NA 49104
#define NC 80
#define THREADS 256
#define NC4 (NC / 4)                 // 20 float4 per anchor
#define NBLK 512                     // persistent blocks; 3 tiles each (512*3 = 1536)
#define BPI 64                       // blocks per image (512/8)
#define KNEG (-0.75f * 0.69314718055994530942f)   // -0.75*ln2 (lg2-domain scale)

// global accumulators (zero at module load; last block resets for next replay)
__device__ double       g_cls[NB];
__device__ double       g_reg[NB];
__device__ int          g_npos[NB];
__device__ unsigned int g_done = 0;

__global__ __launch_bounds__(THREADS)
void fl_kernel(const float* __restrict__ boxes,      // [B,M,4] (x1,y1,x2,y2)
               const int*   __restrict__ labels,     // [B,M]
               const float* __restrict__ anchors,    // [1,A,4] (y1,x1,y2,x2)
               const float* __restrict__ cls,        // [B,A,C]
               const float* __restrict__ reg,        // [B,A,4]
               float*       __restrict__ out)        // [2]
{
    __shared__ float4 s_box[NM];
    __shared__ float  s_barea[NM];
    __shared__ int    s_lab[NM];
    __shared__ float  s_c[THREADS / 32];
    __shared__ float  s_r[THREADS / 32];
    __shared__ int    s_p[THREADS / 32];

    const int x  = blockIdx.x;
    const int b  = x / BPI;              // image: all 3 tiles share it
    const int t0 = x - b * BPI;          // 0..63
    const int t  = threadIdx.x;

    if (t < NM) {
        float4 bx = ((const float4*)boxes)[b * NM + t];
        int lab   = labels[b * NM + t];
        if (lab == 0) {                  // degenerate: inter clamps to 0
            bx = make_float4(3e9f, 3e9f, -3e9f, -3e9f);
            s_barea[t] = 0.0f;
        } else {
            s_barea[t] = (bx.z - bx.x) * (bx.w - bx.y);
        }
        s_box[t] = bx;
        s_lab[t] = lab;
    }
    __syncthreads();

    const int swap = (t >> 5) & 1;       // odd warps run stream phase first
    float lgsum = 0.0f;                  // lg2-domain negative-term accumulator
    float poscls = 0.0f;                 // positive focal terms (sparse)
    float regsum = 0.0f;
    int   nposv  = 0;

    #pragma unroll 1
    for (int item = 0; item < 3; item++) {
        const int abase = (t0 + item * BPI) * THREADS;

        #pragma unroll 1
        for (int ph = 0; ph < 2; ph++) {
            if ((ph ^ swap) == 0) {
                // ============ ASSIGN: ratio argmax (div-free) + reg + correction ============
                const int a = abase + t;
                if (a < NA) {
                    float4 an = ((const float4*)anchors)[a];   // y1,x1,y2,x2
                    const float ay1 = an.x, ax1 = an.y, ay2 = an.z, ax2 = an.w;
                    const float a_area = (ay2 - ay1) * (ax2 - ax1);

                    // maximize I/S (monotone with IoU = I/(S-I), S > 0)
                    float bI = -1.0f, bS = 1.0f; int bidx = 0;
                    #pragma unroll 16
                    for (int m = 0; m < NM; m++) {
                        float4 bx = s_box[m];                  // x1,y1,x2,y2
                        float S  = a_area + s_barea[m];
                        float iw = fminf(ax2, bx.z) - fmaxf(ax1, bx.x);
                        float ih = fminf(ay2, bx.w) - fmaxf(ay1, bx.y);
                        iw = fmaxf(iw, 0.0f); ih = fmaxf(ih, 0.0f);
                        float I = iw * ih;
                        if (I * bS > bI * S) { bI = I; bS = S; bidx = m; }
                    }
                    float ua = fmaxf(bS - bI, 1e-8f);          // reference's exact ua
                    float iou_max = bI / ua;                   // one IEEE divide/anchor

                    float4 ab = s_box[bidx];
                    float  bw = ab.z - ab.x, bh = ab.w - ab.y;
                    bool   big = (bw * bh) > 100.0f;
                    bool   pos = big ? (iou_max >= 0.5f) : (iou_max >= 0.15f);

                    if (pos) {
                        nposv++;
                        float gcx = ab.x + 0.5f * bw, gcy = ab.y + 0.5f * bh;
                        float gw = fmaxf(bw, 1.0f), gh = fmaxf(bh, 1.0f);
                        float aw = ax2 - ax1, ah = ay2 - ay1;
                        float acx = ax1 + 0.5f * aw, acy = ay1 + 0.5f * ah;
                        float tt0 = (gcy - acy) / ah;
                        float tt1 = (gcx - acx) / aw;
                        float tt2 = logf(gh / ah);
                        float tt3 = logf(gw / aw);
                        float4 r = ((const float4*)reg)[(size_t)b * NA + a];
                        float d;
                        d = fabsf(tt0 - r.x); regsum += (d <= 1.0f/9.0f) ? 4.5f*d*d : d - 0.5f/9.0f;
                        d = fabsf(tt1 - r.y); regsum += (d <= 1.0f/9.0f) ? 4.5f*d*d : d - 0.5f/9.0f;
                        d = fabsf(tt2 - r.z); regsum += (d <= 1.0f/9.0f) ? 4.5f*d*d : d - 0.5f/9.0f;
                        d = fabsf(tt3 - r.w); regsum += (d <= 1.0f/9.0f) ? 4.5f*d*d : d - 0.5f/9.0f;

                        // cls correction: add positive term, cancel the stream's neg term
                        int al = s_lab[bidx] - 1;              // in [0, NC)
                        float v = cls[((size_t)b * NA + a) * NC + al];
                        float p = fminf(fmaxf(v, 1e-4f), 1.0f - 1e-4f);
                        float om = 1.0f - p;
                        poscls += 0.25f * om * om * (-__logf(p));
                        lgsum   = fmaf(-(p * p), __log2f(om), lgsum);
                    }
                }
            } else {
                // ============ STREAM: negative focal term (lg2 domain) ============
                int maxa = NA - abase; if (maxa > THREADS) maxa = THREADS;
                const float4* __restrict__ cp =
                    (const float4*)(cls + ((size_t)b * NA + abase) * NC);
                float s0 = 0.0f, s1 = 0.0f, s2 = 0.0f, s3 = 0.0f;
                if (maxa == THREADS) {
                    #pragma unroll
                    for (int k = 0; k < NC4; k++) {
                        float4 v = cp[t + k * THREADS];
                        float p0 = fminf(fmaxf(v.x, 1e-4f), 1.0f - 1e-4f);
                        float p1 = fminf(fmaxf(v.y, 1e-4f), 1.0f - 1e-4f);
                        float p2 = fminf(fmaxf(v.z, 1e-4f), 1.0f - 1e-4f);
                        float p3 = fminf(fmaxf(v.w, 1e-4f), 1.0f - 1e-4f);
                        s0 = fmaf(p0 * p0, __log2f(1.0f - p0), s0);
                        s1 = fmaf(p1 * p1, __log2f(1.0f - p1), s1);
                        s2 = fmaf(p2 * p2, __log2f(1.0f - p2), s2);
                        s3 = fmaf(p3 * p3, __log2f(1.0f - p3), s3);
                    }
                } else {
                    const int nvec = maxa * NC4;
                    #pragma unroll 4
                    for (int i = t; i < nvec; i += THREADS) {
                        float4 v = cp[i];
                        float p0 = fminf(fmaxf(v.x, 1e-4f), 1.0f - 1e-4f);
                        float p1 = fminf(fmaxf(v.y, 1e-4f), 1.0f - 1e-4f);
                        float p2 = fminf(fmaxf(v.z, 1e-4f), 1.0f - 1e-4f);
                        float p3 = fminf(fmaxf(v.w, 1e-4f), 1.0f - 1e-4f);
                        s0 = fmaf(p0 * p0, __log2f(1.0f - p0), s0);
                        s1 = fmaf(p1 * p1, __log2f(1.0f - p1), s1);
                        s2 = fmaf(p2 * p2, __log2f(1.0f - p2), s2);
                        s3 = fmaf(p3 * p3, __log2f(1.0f - p3), s3);
                    }
                }
                lgsum += (s0 + s1) + (s2 + s3);
            }
        }
    }

    // ---------------- block reduction + commit ----------------
    float my_cls = fmaf(KNEG, lgsum, poscls);
    float my_reg = regsum;
    int   my_pos = nposv;
    #pragma unroll
    for (int o = 16; o; o >>= 1) {
        my_cls += __shfl_down_sync(0xFFFFFFFFu, my_cls, o);
        my_reg += __shfl_down_sync(0xFFFFFFFFu, my_reg, o);
        my_pos += __shfl_down_sync(0xFFFFFFFFu, my_pos, o);
    }
    const int wid = t >> 5, lid = t & 31;
    if (lid == 0) { s_c[wid] = my_cls; s_r[wid] = my_reg; s_p[wid] = my_pos; }
    __syncthreads();
    if (wid == 0) {
        const int nw = THREADS / 32;
        float c = (lid < nw) ? s_c[lid] : 0.0f;
        float r = (lid < nw) ? s_r[lid] : 0.0f;
        int   p = (lid < nw) ? s_p[lid] : 0;
        #pragma unroll
        for (int o = 16; o; o >>= 1) {
            c += __shfl_down_sync(0xFFFFFFFFu, c, o);
            r += __shfl_down_sync(0xFFFFFFFFu, r, o);
            p += __shfl_down_sync(0xFFFFFFFFu, p, o);
        }
        if (lid == 0) {
            atomicAdd(&g_cls[b], (double)c);
            if (r != 0.0f) atomicAdd(&g_reg[b], (double)r);
            if (p)         atomicAdd(&g_npos[b], p);
            __threadfence();
            unsigned int ticket = atomicAdd(&g_done, 1u);
            if (ticket == (unsigned int)(NBLK - 1)) {
                // last block: finalize + reset for next graph replay
                double cs = 0.0, rs = 0.0;
                #pragma unroll
                for (int i = 0; i < NB; i++) {
                    double gc = atomicAdd(&g_cls[i], 0.0);   // atomic read
                    double gr = atomicAdd(&g_reg[i], 0.0);
                    int    np = atomicAdd(&g_npos[i], 0);
                    double den = (double)(np > 1 ? np : 1);
                    cs += gc / den;
                    rs += (np > 0) ? (gr / (4.0 * den)) : 0.0;
                    g_cls[i] = 0.0; g_reg[i] = 0.0; g_npos[i] = 0;
                }
                out[0] = (float)(cs / (double)NB);
                out[1] = (float)(rs / (double)NB * 50.0);
                __threadfence();
                g_done = 0;
            }
        }
    }
}

extern "C" void kernel_launch(void* const* d_in, const int* in_sizes, int n_in,
                              void* d_out, int out_size) {
    const float* boxes   = (const float*)d_in[0];
    const int*   labels  = (const int*)  d_in[1];
    const float* anchors = (const float*)d_in[2];
    const float* cls     = (const float*)d_in[3];
    const float* reg     = (const float*)d_in[4];
    float* out = (float*)d_out;

    fl_kernel<<<NBLK, THREADS>>>(boxes, labels, anchors, cls, reg, out);
}

// round 7
// speedup vs baseline: 1.1887x; 1.1887x over previous
#include <cuda_runtime.h>
#include <math.h>

#define NB 8
#define NM 64
#define NA 49104
#define NC 80
#define THREADS 256
#define NA_TILES 192                 // ceil(NA / 256)
#define NAB (NA_TILES * NB)          // 1536 assign blocks
#define NSPI 148                     // stream blocks per image
#define NSB (NSPI * NB)              // 1184 stream blocks
#define TOTB (NAB + NSB)             // 2720
#define VEC (NA * (NC / 4))          // float4s per image = 982080
#define SSTRIDE (NSPI * THREADS)
#define KNEG (-0.75f * 0.69314718055994530942f)   // -0.75*ln2 (lg2-domain scale)

// global accumulators (zero at module load; last block resets for next replay)
__device__ double       g_cls[NB];
__device__ double       g_reg[NB];
__device__ int          g_npos[NB];
__device__ unsigned int g_done = 0;

__device__ __forceinline__ void commit(float c, float r, int p, int b,
                                       float* s_c, float* s_r, int* s_p,
                                       float* __restrict__ out) {
    #pragma unroll
    for (int o = 16; o; o >>= 1) {
        c += __shfl_down_sync(0xFFFFFFFFu, c, o);
        r += __shfl_down_sync(0xFFFFFFFFu, r, o);
        p += __shfl_down_sync(0xFFFFFFFFu, p, o);
    }
    const int wid = threadIdx.x >> 5, lid = threadIdx.x & 31;
    if (lid == 0) { s_c[wid] = c; s_r[wid] = r; s_p[wid] = p; }
    __syncthreads();
    if (wid == 0) {
        const int nw = THREADS / 32;
        c = (lid < nw) ? s_c[lid] : 0.0f;
        r = (lid < nw) ? s_r[lid] : 0.0f;
        p = (lid < nw) ? s_p[lid] : 0;
        #pragma unroll
        for (int o = 16; o; o >>= 1) {
            c += __shfl_down_sync(0xFFFFFFFFu, c, o);
            r += __shfl_down_sync(0xFFFFFFFFu, r, o);
            p += __shfl_down_sync(0xFFFFFFFFu, p, o);
        }
        if (lid == 0) {
            atomicAdd(&g_cls[b], (double)c);
            if (r != 0.0f) atomicAdd(&g_reg[b], (double)r);
            if (p)         atomicAdd(&g_npos[b], p);
            __threadfence();
            unsigned int ticket = atomicAdd(&g_done, 1u);
            if (ticket == (unsigned int)(TOTB - 1)) {
                double cs = 0.0, rs = 0.0;
                #pragma unroll
                for (int i = 0; i < NB; i++) {
                    double gc = atomicAdd(&g_cls[i], 0.0);   // atomic read
                    double gr = atomicAdd(&g_reg[i], 0.0);
                    int    np = atomicAdd(&g_npos[i], 0);
                    double den = (double)(np > 1 ? np : 1);
                    cs += gc / den;
                    rs += (np > 0) ? (gr / (4.0 * den)) : 0.0;
                    g_cls[i] = 0.0; g_reg[i] = 0.0; g_npos[i] = 0;
                }
                out[0] = (float)(cs / (double)NB);
                out[1] = (float)(rs / (double)NB * 50.0);
                __threadfence();
                g_done = 0;
            }
        }
    }
}

__global__ __launch_bounds__(THREADS)
void fl_kernel(const float* __restrict__ boxes,      // [B,M,4] (x1,y1,x2,y2)
               const int*   __restrict__ labels,     // [B,M]
               const float* __restrict__ anchors,    // [1,A,4] (y1,x1,y2,x2)
               const float* __restrict__ cls,        // [B,A,C]
               const float* __restrict__ reg,        // [B,A,4]
               float*       __restrict__ out)        // [2]
{
    __shared__ float4 s_box[NM];
    __shared__ float  s_barea[NM];
    __shared__ int    s_lab[NM];
    __shared__ float  s_c[THREADS / 32];
    __shared__ float  s_r[THREADS / 32];
    __shared__ int    s_p[THREADS / 32];

    const int gid = blockIdx.x;
    const int t   = threadIdx.x;

    // interleave roles so assign (issue-bound) and stream (DRAM-bound) co-reside
    int role, idx;
    if (gid < 2 * NSB) { role = gid & 1; idx = gid >> 1; }
    else               { role = 0;       idx = NSB + (gid - 2 * NSB); }

    if (role == 1) {
        // ============ STREAM: negative focal term over [A,C], lg2 domain ============
        const int b   = idx / NSPI;
        const int blk = idx - b * NSPI;
        const float4* __restrict__ cp = (const float4*)(cls + (size_t)b * NA * NC);
        const int tid = blk * THREADS + t;

        float s0 = 0.0f, s1 = 0.0f, s2 = 0.0f, s3 = 0.0f;
        #pragma unroll 4
        for (int i = tid; i < VEC; i += SSTRIDE) {
            float4 v = cp[i];
            float p0 = fminf(fmaxf(v.x, 1e-4f), 1.0f - 1e-4f);
            float p1 = fminf(fmaxf(v.y, 1e-4f), 1.0f - 1e-4f);
            float p2 = fminf(fmaxf(v.z, 1e-4f), 1.0f - 1e-4f);
            float p3 = fminf(fmaxf(v.w, 1e-4f), 1.0f - 1e-4f);
            s0 = fmaf(p0 * p0, __log2f(1.0f - p0), s0);
            s1 = fmaf(p1 * p1, __log2f(1.0f - p1), s1);
            s2 = fmaf(p2 * p2, __log2f(1.0f - p2), s2);
            s3 = fmaf(p3 * p3, __log2f(1.0f - p3), s3);
        }
        float csum = KNEG * ((s0 + s1) + (s2 + s3));
        commit(csum, 0.0f, 0, b, s_c, s_r, s_p, out);
        return;
    }

    // ============ ASSIGN: ratio argmax (2-chain) + reg loss + sparse correction ============
    const int b    = idx / NA_TILES;
    const int tile = idx - b * NA_TILES;

    if (t < NM) {
        float4 bx = ((const float4*)boxes)[b * NM + t];
        int lab   = labels[b * NM + t];
        if (lab == 0) {                          // degenerate: inter clamps to 0
            bx = make_float4(3e9f, 3e9f, -3e9f, -3e9f);
            s_barea[t] = 0.0f;
        } else {
            s_barea[t] = (bx.z - bx.x) * (bx.w - bx.y);
        }
        s_box[t] = bx;
        s_lab[t] = lab;
    }
    __syncthreads();

    const int a = tile * THREADS + t;
    float my_reg = 0.0f, my_cls = 0.0f;
    int   my_pos = 0;

    if (a < NA) {
        float4 an = ((const float4*)anchors)[a];   // y1,x1,y2,x2
        const float ay1 = an.x, ax1 = an.y, ay2 = an.z, ax2 = an.w;
        const float a_area = (ay2 - ay1) * (ax2 - ax1);

        // two independent argmax chains over even/odd boxes (maximize I/S)
        float bI0 = -1.0f, bS0 = 1.0f; int bi0 = 0;
        float bI1 = -1.0f, bS1 = 1.0f; int bi1 = 1;
        #pragma unroll 8
        for (int m = 0; m < NM; m += 2) {
            {
                float4 bx = s_box[m];
                float S  = a_area + s_barea[m];
                float iw = fminf(ax2, bx.z) - fmaxf(ax1, bx.x);
                float ih = fminf(ay2, bx.w) - fmaxf(ay1, bx.y);
                iw = fmaxf(iw, 0.0f); ih = fmaxf(ih, 0.0f);
                float I = iw * ih;
                if (I * bS0 > bI0 * S) { bI0 = I; bS0 = S; bi0 = m; }
            }
            {
                float4 bx = s_box[m + 1];
                float S  = a_area + s_barea[m + 1];
                float iw = fminf(ax2, bx.z) - fmaxf(ax1, bx.x);
                float ih = fminf(ay2, bx.w) - fmaxf(ay1, bx.y);
                iw = fmaxf(iw, 0.0f); ih = fmaxf(ih, 0.0f);
                float I = iw * ih;
                if (I * bS1 > bI1 * S) { bI1 = I; bS1 = S; bi1 = m + 1; }
            }
        }
        // merge: odd chain wins only with STRICTLY larger ratio (preserves first-max)
        float bI = bI0, bS = bS0; int bidx = bi0;
        if (bI1 * bS0 > bI0 * bS1) { bI = bI1; bS = bS1; bidx = bi1; }

        float ua = fmaxf(bS - bI, 1e-8f);          // reference's exact ua
        float iou_max = bI / ua;                   // one IEEE divide per anchor

        float4 ab = s_box[bidx];
        float  bw = ab.z - ab.x, bh = ab.w - ab.y;
        bool   big = (bw * bh) > 100.0f;
        bool   pos = big ? (iou_max >= 0.5f) : (iou_max >= 0.15f);

        if (pos) {
            my_pos = 1;
            float gcx = ab.x + 0.5f * bw, gcy = ab.y + 0.5f * bh;
            float gw = fmaxf(bw, 1.0f), gh = fmaxf(bh, 1.0f);
            float aw = ax2 - ax1, ah = ay2 - ay1;
            float acx = ax1 + 0.5f * aw, acy = ay1 + 0.5f * ah;
            float tt0 = (gcy - acy) / ah;
            float tt1 = (gcx - acx) / aw;
            float tt2 = logf(gh / ah);
            float tt3 = logf(gw / aw);
            float4 r = ((const float4*)reg)[(size_t)b * NA + a];
            float d;
            d = fabsf(tt0 - r.x); my_reg += (d <= 1.0f/9.0f) ? 4.5f*d*d : d - 0.5f/9.0f;
            d = fabsf(tt1 - r.y); my_reg += (d <= 1.0f/9.0f) ? 4.5f*d*d : d - 0.5f/9.0f;
            d = fabsf(tt2 - r.z); my_reg += (d <= 1.0f/9.0f) ? 4.5f*d*d : d - 0.5f/9.0f;
            d = fabsf(tt3 - r.w); my_reg += (d <= 1.0f/9.0f) ? 4.5f*d*d : d - 0.5f/9.0f;

            // cls correction: + positive term, MINUS the neg term the stream added.
            // stream adds KNEG * p^2 * lg2(om) for this element -> subtract exactly that.
            int al = s_lab[bidx] - 1;              // in [0, NC)
            float v = cls[((size_t)b * NA + a) * NC + al];
            float p = fminf(fmaxf(v, 1e-4f), 1.0f - 1e-4f);
            float om = 1.0f - p;
            float neg_term = KNEG * (p * p) * __log2f(om);   // what the stream added (>0)
            my_cls = 0.25f * om * om * (-__logf(p)) - neg_term;
        }
    }
    commit(my_cls, my_reg, my_pos, b, s_c, s_r, s_p, out);
}

extern "C" void kernel_launch(void* const* d_in, const int* in_sizes, int n_in,
                              void* d_out, int out_size) {
    const float* boxes   = (const float*)d_in[0];
    const int*   labels  = (const int*)  d_in[1];
    const float* anchors = (const float*)d_in[2];
    const float* cls     = (const float*)d_in[3];
    const float* reg     = (const float*)d_in[4];
    float* out = (float*)d_out;

    fl_kernel<<<TOTB, THREADS>>>(boxes, labels, anchors, cls, reg, out);
}

// round 9
// speedup vs baseline: 1.1896x; 1.0007x over previous
#include <cuda_runtime.h>
#include <math.h>

#define NB 8
#define NM 64
#define NP (NM / 2)                  // 32 box pairs
#define NA 49104
#define NC 80
#define THREADS 256
#define NA_TILES 192                 // ceil(NA / 256)
#define NAB (NA_TILES * NB)          // 1536 assign blocks
#define NSPI 148                     // stream blocks per image
#define NSB (NSPI * NB)              // 1184 stream blocks
#define TOTB (NAB + NSB)             // 2720
#define VEC (NA * (NC / 4))          // float4s per image = 982080
#define SSTRIDE (NSPI * THREADS)
#define KNEG (-0.75f * 0.69314718055994530942f)   // -0.75*ln2 (lg2-domain scale)

typedef unsigned long long u64;

// packed f32x2 ops available on sm_100a (min/max.f32x2 are NOT -- sm_103a only)
#define F2ADD(d, a, b)    asm("add.rn.f32x2 %0, %1, %2;"     : "=l"(d) : "l"(a), "l"(b))
#define F2MUL(d, a, b)    asm("mul.rn.f32x2 %0, %1, %2;"     : "=l"(d) : "l"(a), "l"(b))
#define F2FMA(d, a, b, c) asm("fma.rn.f32x2 %0, %1, %2, %3;" : "=l"(d) : "l"(a), "l"(b), "l"(c))
#define F2PK(d, lo, hi)   asm("mov.b64 %0, {%1, %2};"        : "=l"(d) : "f"(lo), "f"(hi))
#define F2UP(lo, hi, s)   asm("mov.b64 {%0, %1}, %2;"        : "=f"(lo), "=f"(hi) : "l"(s))

__device__ __forceinline__ u64 pk2c(float lo, float hi) {   // constexpr-ish pack
    return (u64)__float_as_uint(lo) | ((u64)__float_as_uint(hi) << 32);
}

// global accumulators (zero at module load; last block resets for next replay)
__device__ double       g_cls[NB];
__device__ double       g_reg[NB];
__device__ int          g_npos[NB];
__device__ unsigned int g_done = 0;

__device__ __forceinline__ void commit(float c, float r, int p, int b,
                                       float* s_c, float* s_r, int* s_p,
                                       float* __restrict__ out) {
    #pragma unroll
    for (int o = 16; o; o >>= 1) {
        c += __shfl_down_sync(0xFFFFFFFFu, c, o);
        r += __shfl_down_sync(0xFFFFFFFFu, r, o);
        p += __shfl_down_sync(0xFFFFFFFFu, p, o);
    }
    const int wid = threadIdx.x >> 5, lid = threadIdx.x & 31;
    if (lid == 0) { s_c[wid] = c; s_r[wid] = r; s_p[wid] = p; }
    __syncthreads();
    if (wid == 0) {
        const int nw = THREADS / 32;
        c = (lid < nw) ? s_c[lid] : 0.0f;
        r = (lid < nw) ? s_r[lid] : 0.0f;
        p = (lid < nw) ? s_p[lid] : 0;
        #pragma unroll
        for (int o = 16; o; o >>= 1) {
            c += __shfl_down_sync(0xFFFFFFFFu, c, o);
            r += __shfl_down_sync(0xFFFFFFFFu, r, o);
            p += __shfl_down_sync(0xFFFFFFFFu, p, o);
        }
        if (lid == 0) {
            atomicAdd(&g_cls[b], (double)c);
            if (r != 0.0f) atomicAdd(&g_reg[b], (double)r);
            if (p)         atomicAdd(&g_npos[b], p);
            __threadfence();
            unsigned int ticket = atomicAdd(&g_done, 1u);
            if (ticket == (unsigned int)(TOTB - 1)) {
                double cs = 0.0, rs = 0.0;
                #pragma unroll
                for (int i = 0; i < NB; i++) {
                    double gc = atomicAdd(&g_cls[i], 0.0);   // atomic read
                    double gr = atomicAdd(&g_reg[i], 0.0);
                    int    np = atomicAdd(&g_npos[i], 0);
                    double den = (double)(np > 1 ? np : 1);
                    cs += gc / den;
                    rs += (np > 0) ? (gr / (4.0 * den)) : 0.0;
                    g_cls[i] = 0.0; g_reg[i] = 0.0; g_npos[i] = 0;
                }
                out[0] = (float)(cs / (double)NB);
                out[1] = (float)(rs / (double)NB * 50.0);
                __threadfence();
                g_done = 0;
            }
        }
    }
}

__global__ __launch_bounds__(THREADS)
void fl_kernel(const float* __restrict__ boxes,      // [B,M,4] (x1,y1,x2,y2)
               const int*   __restrict__ labels,     // [B,M]
               const float* __restrict__ anchors,    // [1,A,4] (y1,x1,y2,x2)
               const float* __restrict__ cls,        // [B,A,C]
               const float* __restrict__ reg,        // [B,A,4]
               float*       __restrict__ out)        // [2]
{
    __shared__ float4 s_box[NM];
    __shared__ int    s_lab[NM];
    __shared__ float4 s_zx[NP];   // (z_e, z_o, -x_e, -x_o)
    __shared__ float4 s_wy[NP];   // (w_e, w_o, -y_e, -y_o)
    __shared__ u64    s_ba[NP];   // packed (barea_e, barea_o)
    __shared__ float  s_c[THREADS / 32];
    __shared__ float  s_r[THREADS / 32];
    __shared__ int    s_p[THREADS / 32];

    const int gid = blockIdx.x;
    const int t   = threadIdx.x;

    // interleave roles so assign (issue-bound) and stream (DRAM-bound) co-reside
    int role, idx;
    if (gid < 2 * NSB) { role = gid & 1; idx = gid >> 1; }
    else               { role = 0;       idx = NSB + (gid - 2 * NSB); }

    if (role == 1) {
        // ============ STREAM: negative focal term over [A,C], lg2 domain ============
        const int b   = idx / NSPI;
        const int blk = idx - b * NSPI;
        const float4* __restrict__ cp = (const float4*)(cls + (size_t)b * NA * NC);
        const int tid = blk * THREADS + t;

        const u64 one2  = pk2c(1.0f, 1.0f);
        const u64 none2 = pk2c(-1.0f, -1.0f);
        u64 acc01 = 0ull, acc23 = 0ull;          // packed (0.0, 0.0)
        #pragma unroll 4
        for (int i = tid; i < VEC; i += SSTRIDE) {
            float4 v = cp[i];
            float p0 = fminf(fmaxf(v.x, 1e-4f), 1.0f - 1e-4f);
            float p1 = fminf(fmaxf(v.y, 1e-4f), 1.0f - 1e-4f);
            float p2 = fminf(fmaxf(v.z, 1e-4f), 1.0f - 1e-4f);
            float p3 = fminf(fmaxf(v.w, 1e-4f), 1.0f - 1e-4f);
            u64 p01, p23, pp01, pp23, om01, om23, l01, l23;
            F2PK(p01, p0, p1); F2PK(p23, p2, p3);
            F2MUL(pp01, p01, p01);               // p^2
            F2MUL(pp23, p23, p23);
            F2FMA(om01, p01, none2, one2);       // 1 - p (exact, same as FADD)
            F2FMA(om23, p23, none2, one2);
            float o0, o1, o2, o3;
            F2UP(o0, o1, om01); F2UP(o2, o3, om23);
            F2PK(l01, __log2f(o0), __log2f(o1));
            F2PK(l23, __log2f(o2), __log2f(o3));
            F2FMA(acc01, pp01, l01, acc01);      // acc += p^2 * lg2(1-p)
            F2FMA(acc23, pp23, l23, acc23);
        }
        float a0, a1, a2, a3;
        F2UP(a0, a1, acc01); F2UP(a2, a3, acc23);
        float csum = KNEG * ((a0 + a1) + (a2 + a3));
        commit(csum, 0.0f, 0, b, s_c, s_r, s_p, out);
        return;
    }

    // ============ ASSIGN: f32x2-assisted IoU + exact ratio argmax + reg + correction ============
    const int b    = idx / NA_TILES;
    const int tile = idx - b * NA_TILES;

    if (t < NM) {
        float4 bx = ((const float4*)boxes)[b * NM + t];
        int lab   = labels[b * NM + t];
        if (lab == 0)                            // degenerate: inter clamps to 0
            bx = make_float4(3e9f, 3e9f, -3e9f, -3e9f);
        s_box[t] = bx;
        s_lab[t] = lab;
    }
    if (t < NP) {                                // pack pair q = t (boxes 2q, 2q+1)
        float4 e = ((const float4*)boxes)[b * NM + 2 * t];
        float4 o = ((const float4*)boxes)[b * NM + 2 * t + 1];
        int le = labels[b * NM + 2 * t], lo = labels[b * NM + 2 * t + 1];
        float bae, bao;
        if (le == 0) { e = make_float4(3e9f, 3e9f, -3e9f, -3e9f); bae = 0.0f; }
        else bae = (e.z - e.x) * (e.w - e.y);
        if (lo == 0) { o = make_float4(3e9f, 3e9f, -3e9f, -3e9f); bao = 0.0f; }
        else bao = (o.z - o.x) * (o.w - o.y);
        s_zx[t] = make_float4(e.z, o.z, -e.x, -o.x);
        s_wy[t] = make_float4(e.w, o.w, -e.y, -o.y);
        s_ba[t] = pk2c(bae, bao);
    }
    __syncthreads();

    const int a = tile * THREADS + t;
    float my_reg = 0.0f, my_cls = 0.0f;
    int   my_pos = 0;

    if (a < NA) {
        float4 an = ((const float4*)anchors)[a];   // y1,x1,y2,x2
        const float ay1 = an.x, ax1 = an.y, ay2 = an.z, ax2 = an.w;
        const float nax1 = -ax1, nay1 = -ay1;
        const float a_area = (ay2 - ay1) * (ax2 - ax1);
        u64 aar2; F2PK(aar2, a_area, a_area);

        // two argmax chains: lo = even boxes (2q), hi = odd (2q+1); exact cross-mult compare
        float bI0 = -1.0f, bS0 = 1.0f; int bq0 = 0;
        float bI1 = -1.0f, bS1 = 1.0f; int bq1 = 0;
        #pragma unroll 8
        for (int q = 0; q < NP; q++) {
            float4 zx = s_zx[q];                 // z_e,z_o,-x_e,-x_o
            float4 wy = s_wy[q];                 // w_e,w_o,-y_e,-y_o
            u64 ba = s_ba[q];
            u64 t1, t2, iw2, ih2, I2, S2;
            F2PK(t1, fminf(ax2,  zx.x), fminf(ax2,  zx.y));
            F2PK(t2, fminf(nax1, zx.z), fminf(nax1, zx.w));
            F2ADD(iw2, t1, t2);                  // min(ax2,z) - max(ax1,x), both lanes
            F2PK(t1, fminf(ay2,  wy.x), fminf(ay2,  wy.y));
            F2PK(t2, fminf(nay1, wy.z), fminf(nay1, wy.w));
            F2ADD(ih2, t1, t2);
            float iw0, iw1, ih0, ih1;
            F2UP(iw0, iw1, iw2); F2UP(ih0, ih1, ih2);
            u64 iwc, ihc;
            F2PK(iwc, fmaxf(iw0, 0.0f), fmaxf(iw1, 0.0f));
            F2PK(ihc, fmaxf(ih0, 0.0f), fmaxf(ih1, 0.0f));
            F2MUL(I2, iwc, ihc);
            F2ADD(S2, aar2, ba);
            float I0, I1, S0, S1;
            F2UP(I0, I1, I2); F2UP(S0, S1, S2);
            if (I0 * bS0 > bI0 * S0) { bI0 = I0; bS0 = S0; bq0 = q; }
            if (I1 * bS1 > bI1 * S1) { bI1 = I1; bS1 = S1; bq1 = q; }
        }
        // merge: odd chain wins only with STRICTLY larger ratio (first-max preserved)
        float bI = bI0, bS = bS0; int bidx = 2 * bq0;
        if (bI1 * bS0 > bI0 * bS1) { bI = bI1; bS = bS1; bidx = 2 * bq1 + 1; }

        float ua = fmaxf(bS - bI, 1e-8f);          // reference's exact ua
        float iou_max = bI / ua;                   // one IEEE divide per anchor

        float4 ab = s_box[bidx];
        float  bw = ab.z - ab.x, bh = ab.w - ab.y;
        bool   big = (bw * bh) > 100.0f;
        bool   pos = big ? (iou_max >= 0.5f) : (iou_max >= 0.15f);

        if (pos) {
            my_pos = 1;
            float gcx = ab.x + 0.5f * bw, gcy = ab.y + 0.5f * bh;
            float gw = fmaxf(bw, 1.0f), gh = fmaxf(bh, 1.0f);
            float aw = ax2 - ax1, ah = ay2 - ay1;
            float acx = ax1 + 0.5f * aw, acy = ay1 + 0.5f * ah;
            float tt0 = (gcy - acy) / ah;
            float tt1 = (gcx - acx) / aw;
            float tt2 = logf(gh / ah);
            float tt3 = logf(gw / aw);
            float4 r = ((const float4*)reg)[(size_t)b * NA + a];
            float d;
            d = fabsf(tt0 - r.x); my_reg += (d <= 1.0f/9.0f) ? 4.5f*d*d : d - 0.5f/9.0f;
            d = fabsf(tt1 - r.y); my_reg += (d <= 1.0f/9.0f) ? 4.5f*d*d : d - 0.5f/9.0f;
            d = fabsf(tt2 - r.z); my_reg += (d <= 1.0f/9.0f) ? 4.5f*d*d : d - 0.5f/9.0f;
            d = fabsf(tt3 - r.w); my_reg += (d <= 1.0f/9.0f) ? 4.5f*d*d : d - 0.5f/9.0f;

            // cls correction: + positive term, MINUS the neg term the stream added
            int al = s_lab[bidx] - 1;              // in [0, NC)
            float v = cls[((size_t)b * NA + a) * NC + al];
            float p = fminf(fmaxf(v, 1e-4f), 1.0f - 1e-4f);
            float om = 1.0f - p;
            float neg_term = KNEG * (p * p) * __log2f(om);   // what the stream added (>0)
            my_cls = 0.25f * om * om * (-__logf(p)) - neg_term;
        }
    }
    commit(my_cls, my_reg, my_pos, b, s_c, s_r, s_p, out);
}

extern "C" void kernel_launch(void* const* d_in, const int* in_sizes, int n_in,
                              void* d_out, int out_size) {
    const float* boxes   = (const float*)d_in[0];
    const int*   labels  = (const int*)  d_in[1];
    const float* anchors = (const float*)d_in[2];
    const float* cls     = (const float*)d_in[3];
    const float* reg     = (const float*)d_in[4];
    float* out = (float*)d_out;

    fl_kernel<<<TOTB, THREADS>>>(boxes, labels, anchors, cls, reg, out);
}